// round 10
// baseline (speedup 1.0000x reference)
#include <cuda_runtime.h>
#include <cstdint>

#define BATCH 8
#define HS 256
#define WS 256
#define H 512
#define W 512
#define HW (H*W)
#define NITER 5

#define TILE 32
#define HALO 10                 // 2*NITER total dependency radius
#define S 52                    // TILE + 2*HALO
#define SX 64                   // padded smem row stride (power of two)
#define SCELLS (S*SX)           // 3328 = 13 * 256 exactly
#define NCL 13                  // cells per thread, no tail

#define SENT 2.0e30f
#define ENC  0x7FFFFFFF
// interior column masks for frontier words: cols 1..50 only
#define MASK_W0 0xFFFFFFFEu     // clear col 0
#define MASK_W1 0x0007FFFFu     // cols 32..50 = bits 0..18

// ---------------- scratch (static device globals; no runtime allocation) ----------------
// g_win is zero-initialized at module load; k_place restores zeros every run,
// so "g_win == 0 everywhere" holds at k_compute entry on every graph replay.
__device__ int    g_win[BATCH*HW];   // 0 = no winner; else ENC - source_index (atomicMax)
__device__ float2 g_d  [BATCH*HW];
__device__ float2 g_iv [BATCH*HW];   // (-dx,-dy) of winner, or (SENT,SENT) if none

// ---------------- 2x bilinear upsample of (src - base), scale, scatter winner ----------
// One thread computes a 2x2 output quad. Upsample weights are the constants
// {0.25, 0.75}; edge clamping degenerates correctly through clamped cell indices.
__global__ void k_compute(const float2* __restrict__ src, const float2* __restrict__ base) {
    int t = blockIdx.x * blockDim.x + threadIdx.x;
    if (t >= BATCH*HS*WS) return;
    int b  = t >> 16;            // / (256*256)
    int i  = t & 65535;
    int qx = i & 255;
    int qy = i >> 8;

    int c0 = max(qx-1, 0), c1 = qx, c2 = min(qx+1, WS-1);
    int r0 = max(qy-1, 0), r1 = qy, r2 = min(qy+1, HS-1);

    const float2* sb = src + (size_t)b * HS * WS;

    // 3x3 neighborhood of (src - base)
    float2 d[3][3];
    int rows[3] = {r0, r1, r2};
    int cols[3] = {c0, c1, c2};
    #pragma unroll
    for (int a = 0; a < 3; a++) {
        #pragma unroll
        for (int e = 0; e < 3; e++) {
            int o = rows[a]*WS + cols[e];
            float2 s = sb[o], bb = base[o];
            d[a][e] = make_float2(s.x - bb.x, s.y - bb.y);
        }
    }

    // row interps: wy = 0.75 for output row 2qy, wy = 0.25 for output row 2qy+1
    float2 ry0[3], ry1[3];
    #pragma unroll
    for (int e = 0; e < 3; e++) {
        ry0[e] = make_float2(d[0][e].x*0.25f + d[1][e].x*0.75f,
                             d[0][e].y*0.25f + d[1][e].y*0.75f);
        ry1[e] = make_float2(d[1][e].x*0.75f + d[2][e].x*0.25f,
                             d[1][e].y*0.75f + d[2][e].y*0.25f);
    }

    // col interps: wx = 0.75 for output col 2qx, wx = 0.25 for output col 2qx+1
    float2 o00 = make_float2((ry0[0].x*0.25f + ry0[1].x*0.75f) * (0.5f*(float)W),
                             (ry0[0].y*0.25f + ry0[1].y*0.75f) * (0.5f*(float)H));
    float2 o10 = make_float2((ry0[1].x*0.75f + ry0[2].x*0.25f) * (0.5f*(float)W),
                             (ry0[1].y*0.75f + ry0[2].y*0.25f) * (0.5f*(float)H));
    float2 o01 = make_float2((ry1[0].x*0.25f + ry1[1].x*0.75f) * (0.5f*(float)W),
                             (ry1[0].y*0.25f + ry1[1].y*0.75f) * (0.5f*(float)H));
    float2 o11 = make_float2((ry1[1].x*0.75f + ry1[2].x*0.25f) * (0.5f*(float)W),
                             (ry1[1].y*0.75f + ry1[2].y*0.25f) * (0.5f*(float)H));

    // coalesced float4 stores of (dx,dy) pairs
    int x0 = 2*qx, y0 = 2*qy;
    size_t gbase = (size_t)b*HW;
    *(float4*)&g_d[gbase + (size_t)y0*W + x0]     = make_float4(o00.x, o00.y, o10.x, o10.y);
    *(float4*)&g_d[gbase + (size_t)(y0+1)*W + x0] = make_float4(o01.x, o01.y, o11.x, o11.y);

    // scatter winners: round-half-even (rintf), oob check, min source index via max encoding
    #define SCATTER(px, py, vv) do {                                          \
        float fx = rintf((float)(px) + (vv).x);                               \
        float fy = rintf((float)(py) + (vv).y);                               \
        if (fx >= 0.0f && fy >= 0.0f && fx <= (float)(W-1) && fy <= (float)(H-1)) { \
            int ti = (int)gbase + (int)fy * W + (int)fx;                      \
            atomicMax(&g_win[ti], ENC - ((py)*W + (px)));                     \
        }                                                                     \
    } while (0)
    SCATTER(x0,   y0,   o00);
    SCATTER(x0+1, y0,   o10);
    SCATTER(x0,   y0+1, o01);
    SCATTER(x0+1, y0+1, o11);
    #undef SCATTER
}

// ---------------- gather winners -> dense float2 with sentinel; reset g_win ----------------
__global__ void k_place() {
    int t = blockIdx.x * blockDim.x + threadIdx.x;
    if (t >= BATCH*HW) return;
    int e = g_win[t];
    g_win[t] = 0;                          // restore zero-state for the next replay
    int b = t / HW;
    float2 v = make_float2(SENT, SENT);
    if (e != 0) {
        float2 d = g_d[b*HW + (ENC - e)];
        v = make_float2(-d.x, -d.y);
    }
    g_iv[t] = v;
}

// ---------------- fused: 5x dilation (bit frontier + gated conv) + 5x bit erosion ------
// (round-7 verbatim: measured 58.7us)
__global__ __launch_bounds__(256) void k_fused(const float* __restrict__ kw,
                                               const float2* __restrict__ tgt,
                                               float2* __restrict__ out) {
    __shared__ float2             smV[SCELLS];
    __shared__ unsigned long long bmL[S];   // mask bitwords, 64b per row (cols 0..51)
    __shared__ unsigned long long fwL[S];   // frontier bitwords per dilation iter
    __shared__ float              skw[9];

    int b   = blockIdx.z;
    int tx0 = blockIdx.x * TILE - HALO;
    int ty0 = blockIdx.y * TILE - HALO;
    int tid = threadIdx.x;

    if (tid < 9) skw[tid] = kw[tid];

    // thread-invariant column; r for cell j is r0 + 4*j
    const int c    = tid & 63;
    const int r0   = tid >> 6;
    const int half = (tid >> 5) & 1;          // which 32-col word this warp covers

    const float2* giv = g_iv + (size_t)b * HW;

    // ---- load 52x52 tile (zero-extended), build mask bitwords via ballot ----
    #pragma unroll
    for (int j = 0; j < NCL; j++) {
        int idx = tid + j*256;
        int r = r0 + 4*j;
        float2 v = make_float2(0.0f, 0.0f);
        bool m = false;
        if (c < S) {
            int px = tx0 + c, py = ty0 + r;
            if (px >= 0 && px < W && py >= 0 && py < H) {
                float2 g = giv[py*W + px];
                if (g.x != SENT) { v = g; m = true; }
            }
        }
        smV[idx] = v;
        unsigned wball = __ballot_sync(0xffffffffu, m);
        if ((tid & 31) == 0) ((unsigned*)&bmL[r])[half] = wball;
    }
    __syncthreads();

    const bool act = tid < S*2;
    const int  wr  = tid >> 1, wk = tid & 1;

    // ---- 5 dilation iterations ----
    for (int it = 0; it < NITER; it++) {
        // frontier words (104 threads, pure bit ops), pre-masked to interior
        unsigned f = 0u;
        if (act) {
            unsigned cw = ((unsigned*)&bmL[wr])[wk];
            unsigned up = (wr > 0)   ? ((unsigned*)&bmL[wr-1])[wk] : 0u;
            unsigned dn = (wr < S-1) ? ((unsigned*)&bmL[wr+1])[wk] : 0u;
            unsigned lw = (wk == 1)  ? ((unsigned*)&bmL[wr])[0]    : 0u;
            unsigned rw = (wk == 0)  ? ((unsigned*)&bmL[wr])[1]    : 0u;
            f = (up | dn | (cw << 1) | (lw >> 31) | (cw >> 1) | (rw << 31)) & ~cw;
            f &= wk ? MASK_W1 : MASK_W0;
            if (wr == 0 || wr == S-1) f = 0u;
            ((unsigned*)&fwL[wr])[wk] = f;
        }
        __syncthreads();

        // sweep: broadcast frontier-word check; conv only at frontier cells
        #pragma unroll
        for (int j = 0; j < NCL; j++) {
            int r = r0 + 4*j;
            unsigned fword = ((unsigned*)&fwL[r])[c >> 5];   // broadcast within warp
            if ((fword >> (c & 31)) & 1u) {
                int idx = tid + j*256;
                unsigned long long rm = bmL[r-1], rc = bmL[r], rp = bmL[r+1];
                unsigned n0 = (unsigned)(rm >> (c-1)) & 7u;
                unsigned n1 = (unsigned)(rc >> (c-1)) & 7u;   // center bit = 0 by construction
                unsigned n2 = (unsigned)(rp >> (c-1)) & 7u;
                float am = 0.0f, ax = 0.0f, ay = 0.0f;
                #define ACC(bit, kidx, off) \
                    if (bit) { float k = skw[kidx]; float2 v = smV[idx + (off)]; \
                               am += k; ax += k * v.x; ay += k * v.y; }
                ACC(n0 & 1u, 0, -SX-1) ACC(n0 & 2u, 1, -SX) ACC(n0 & 4u, 2, -SX+1)
                ACC(n1 & 1u, 3, -1)                         ACC(n1 & 4u, 5, +1)
                ACC(n2 & 1u, 6,  SX-1) ACC(n2 & 2u, 7,  SX) ACC(n2 & 4u, 8,  SX+1)
                #undef ACC
                smV[idx] = make_float2(ax / am, ay / am);    // own (unset) cell only
            }
        }
        __syncthreads();
        if (act) ((unsigned*)&bmL[wr])[wk] = ((unsigned*)&bmL[wr])[wk] | f;
        __syncthreads();
    }

    // ---- 5 erosion iterations: pure word-level bit ops on 104 threads ----
    for (int it = 0; it < NITER; it++) {
        unsigned nw = 0u;
        if (act) {
            unsigned cw = ((unsigned*)&bmL[wr])[wk];
            unsigned up = (wr > 0)   ? ((unsigned*)&bmL[wr-1])[wk] : 0u;
            unsigned dn = (wr < S-1) ? ((unsigned*)&bmL[wr+1])[wk] : 0u;
            unsigned lw = (wk == 1)  ? ((unsigned*)&bmL[wr])[0]    : 0u;
            unsigned rw = (wk == 0)  ? ((unsigned*)&bmL[wr])[1]    : 0u;
            nw = cw & up & dn & ((cw << 1) | (lw >> 31)) & ((cw >> 1) | (rw << 31));
        }
        __syncthreads();
        if (act) ((unsigned*)&bmL[wr])[wk] = nw;
        __syncthreads();
    }

    // ---- compose interior 32x32, coalesced float2 writes ----
    #pragma unroll
    for (int j = 0; j < (TILE*TILE)/256; j++) {
        int local = tid + j*256;          // 0..1023
        int lyy = local >> 5, lxx = local & 31;
        int rr = lyy + HALO, cc = lxx + HALO;
        bool m = (bmL[rr] >> cc) & 1ull;
        float2 v = smV[rr*SX + cc];
        int py = ty0 + rr, px = tx0 + cc;   // in [0, 512)
        int g = py*W + px;
        float vx = m ? v.x * (2.0f / (float)W) : 4.0f;   // 2*W * (2/W) = 4
        float vy = m ? v.y * (2.0f / (float)H) : 4.0f;
        float2 t2 = tgt[g];
        out[(size_t)b*HW + g] = make_float2(t2.x + vx, t2.y + vy);
    }
}

extern "C" void kernel_launch(void* const* d_in, const int* in_sizes, int n_in,
                              void* d_out, int out_size) {
    // identify inputs by unique element counts (robust to ordering)
    const float* src  = nullptr;   // 8*256*256*2  = 1048576
    const float* kw   = nullptr;   // 3*3          = 9
    const float* base = nullptr;   // 1*256*256*2  = 131072
    const float* tgt  = nullptr;   // 1*512*512*2  = 524288
    for (int j = 0; j < n_in; j++) {
        switch (in_sizes[j]) {
            case 1048576: src  = (const float*)d_in[j]; break;
            case 9:       kw   = (const float*)d_in[j]; break;
            case 131072:  base = (const float*)d_in[j]; break;
            case 524288:  tgt  = (const float*)d_in[j]; break;
            default: break; // niter (size 1) ignored; fixed at 5
        }
    }
    float* out = (float*)d_out;

    const int TB = 256;

    k_compute<<<(BATCH*HS*WS + TB - 1)/TB, TB>>>((const float2*)src, (const float2*)base);
    k_place  <<<(BATCH*HW    + TB - 1)/TB, TB>>>();

    dim3 grid(W/TILE, H/TILE, BATCH);   // 16 x 16 x 8
    k_fused<<<grid, TB>>>(kw, (const float2*)tgt, (float2*)out);
}

// round 11
// speedup vs baseline: 1.8182x; 1.8182x over previous
#include <cuda_runtime.h>
#include <cstdint>

#define BATCH 8
#define HS 256
#define WS 256
#define H 512
#define W 512
#define HW (H*W)
#define NITER 5

#define TILE 32
#define HALO 10                 // 2*NITER total dependency radius
#define S 52                    // TILE + 2*HALO
#define SX 64                   // padded smem row stride (power of two)
#define SCELLS (S*SX)           // 3328 = 13 * 256 exactly
#define NCL 13                  // cells per thread, no tail
#define WLMAX 2500              // frontier <= interior unset cells (50*50)

#define SENT 2.0e30f
// interior column masks for frontier words: cols 1..50 only
#define MASK_W0 0xFFFFFFFEu     // clear col 0
#define MASK_W1 0x0007FFFFu     // cols 32..50 = bits 0..18

// ---------------- scratch (static device globals; no runtime allocation) ----------------
__device__ int    g_win[BATCH*HW];
__device__ float2 g_d  [BATCH*HW];
__device__ float2 g_iv [BATCH*HW];   // (-dx,-dy) of winner, or (SENT,SENT) if none

// ---------------- reset winner array (vectorized) ----------------
__global__ void k_init() {
    int t = blockIdx.x * blockDim.x + threadIdx.x;
    int4* p = (int4*)g_win;
    if (t < (BATCH*HW)/4) p[t] = make_int4(0x7FFFFFFF,0x7FFFFFFF,0x7FFFFFFF,0x7FFFFFFF);
}

// ---------------- bilinear upsample of (src - base), scale, scatter winner ----------------
__global__ void k_compute(const float2* __restrict__ src, const float2* __restrict__ base) {
    int t = blockIdx.x * blockDim.x + threadIdx.x;
    if (t >= BATCH*HW) return;
    int b = t / HW;
    int i = t - b*HW;
    int x = i % W;
    int y = i / W;

    // coords: c = (i+0.5)*(256/512) - 0.5 = 0.5*i - 0.25, clipped to [0, 255]
    float cy = 0.5f * (float)y - 0.25f;
    cy = fminf(fmaxf(cy, 0.0f), 255.0f);
    int ly = (int)floorf(cy);
    int hy = min(ly + 1, HS - 1);
    float wy = cy - (float)ly;

    float cx = 0.5f * (float)x - 0.25f;
    cx = fminf(fmaxf(cx, 0.0f), 255.0f);
    int lx = (int)floorf(cx);
    int hx = min(lx + 1, WS - 1);
    float wx = cx - (float)lx;

    const float2* sb = src + (size_t)b * HS * WS;
    int o00 = ly*WS + lx, o01 = ly*WS + hx, o10 = hy*WS + lx, o11 = hy*WS + hx;

    float2 s00 = sb[o00], s01 = sb[o01], s10 = sb[o10], s11 = sb[o11];
    float2 b00 = base[o00], b01 = base[o01], b10 = base[o10], b11 = base[o11];

    float d00x = s00.x - b00.x, d01x = s01.x - b01.x, d10x = s10.x - b10.x, d11x = s11.x - b11.x;
    float d00y = s00.y - b00.y, d01y = s01.y - b01.y, d10y = s10.y - b10.y, d11y = s11.y - b11.y;

    float r0x = d00x*(1.0f-wy) + d10x*wy;
    float r1x = d01x*(1.0f-wy) + d11x*wy;
    float dx  = (r0x*(1.0f-wx) + r1x*wx) * (0.5f * (float)W);

    float r0y = d00y*(1.0f-wy) + d10y*wy;
    float r1y = d01y*(1.0f-wy) + d11y*wy;
    float dy  = (r0y*(1.0f-wx) + r1y*wx) * (0.5f * (float)H);

    g_d[t] = make_float2(dx, dy);

    // round-half-even (matches jnp.round), oob check, winner = min source index
    float fx = rintf((float)x + dx);
    float fy = rintf((float)y + dy);
    if (fx >= 0.0f && fy >= 0.0f && fx <= (float)(W-1) && fy <= (float)(H-1)) {
        int ti = b*HW + (int)fy * W + (int)fx;
        atomicMin(&g_win[ti], i);
    }
}

// ---------------- gather winners -> dense float2 with sentinel ----------------
__global__ void k_place() {
    int t = blockIdx.x * blockDim.x + threadIdx.x;
    if (t >= BATCH*HW) return;
    int w = g_win[t];
    int b = t / HW;
    float2 v = make_float2(SENT, SENT);
    if (w != 0x7FFFFFFF) {
        float2 d = g_d[b*HW + w];
        v = make_float2(-d.x, -d.y);
    }
    g_iv[t] = v;
}

// ---------------- fused: 5x dilation (bit frontier -> worklist conv) + 5x bit erosion ----
__global__ __launch_bounds__(256) void k_fused(const float* __restrict__ kw,
                                               const float2* __restrict__ tgt,
                                               float2* __restrict__ out) {
    __shared__ float2             smV[SCELLS];
    __shared__ unsigned long long bmL[S];       // mask bitwords, 64b per row (cols 0..51)
    __shared__ unsigned short     wl[WLMAX];    // frontier cell worklist (idx = r*SX + c)
    __shared__ int                wcnt[NITER];  // per-iteration worklist sizes
    __shared__ float              skw[9];

    int b   = blockIdx.z;
    int tx0 = blockIdx.x * TILE - HALO;
    int ty0 = blockIdx.y * TILE - HALO;
    int tid = threadIdx.x;

    if (tid < 9) skw[tid] = kw[tid];
    if (tid < NITER) wcnt[tid] = 0;

    // thread-invariant column; r for cell j is r0 + 4*j
    const int c    = tid & 63;
    const int r0   = tid >> 6;
    const int half = (tid >> 5) & 1;          // which 32-col word this warp covers

    const float2* giv = g_iv + (size_t)b * HW;

    // ---- load 52x52 tile (zero-extended), build mask bitwords via ballot ----
    #pragma unroll
    for (int j = 0; j < NCL; j++) {
        int idx = tid + j*256;
        int r = r0 + 4*j;
        float2 v = make_float2(0.0f, 0.0f);
        bool m = false;
        if (c < S) {
            int px = tx0 + c, py = ty0 + r;
            if (px >= 0 && px < W && py >= 0 && py < H) {
                float2 g = giv[py*W + px];
                if (g.x != SENT) { v = g; m = true; }
            }
        }
        smV[idx] = v;
        unsigned wball = __ballot_sync(0xffffffffu, m);
        if ((tid & 31) == 0) ((unsigned*)&bmL[r])[half] = wball;
    }
    __syncthreads();

    const bool act = tid < S*2;
    const int  wr  = tid >> 1, wk = tid & 1;

    // ---- 5 dilation iterations: frontier bit-phase -> compact worklist -> gated conv ----
    for (int it = 0; it < NITER; it++) {
        // frontier words (104 threads, pure bit ops), pre-masked to interior;
        // reserve worklist slots and emit packed cell indices
        unsigned f = 0u;
        if (act) {
            unsigned cw = ((unsigned*)&bmL[wr])[wk];
            unsigned up = (wr > 0)   ? ((unsigned*)&bmL[wr-1])[wk] : 0u;
            unsigned dn = (wr < S-1) ? ((unsigned*)&bmL[wr+1])[wk] : 0u;
            unsigned lw = (wk == 1)  ? ((unsigned*)&bmL[wr])[0]    : 0u;
            unsigned rw = (wk == 0)  ? ((unsigned*)&bmL[wr])[1]    : 0u;
            f = (up | dn | (cw << 1) | (lw >> 31) | (cw >> 1) | (rw << 31)) & ~cw;
            f &= wk ? MASK_W1 : MASK_W0;
            if (wr == 0 || wr == S-1) f = 0u;
            if (f) {
                int ofs = atomicAdd(&wcnt[it], __popc(f));
                unsigned ff = f;
                int cellbase = wr*SX + wk*32;
                while (ff) {
                    int bit = __ffs(ff) - 1;
                    ff &= ff - 1;
                    wl[ofs++] = (unsigned short)(cellbase + bit);
                }
            }
        }
        __syncthreads();

        // conv only at listed frontier cells, load-balanced across all 256 threads
        int n = wcnt[it];
        for (int k = tid; k < n; k += 256) {
            int idx = wl[k];
            int cc = idx & 63;              // in [1,50]
            int rr = idx >> 6;              // in [1,50]
            unsigned long long rm = bmL[rr-1], rc = bmL[rr], rp = bmL[rr+1];
            unsigned n0 = (unsigned)(rm >> (cc-1)) & 7u;
            unsigned n1 = (unsigned)(rc >> (cc-1)) & 7u;   // center bit = 0 by construction
            unsigned n2 = (unsigned)(rp >> (cc-1)) & 7u;
            float am = 0.0f, ax = 0.0f, ay = 0.0f;
            #define ACC(bit, kidx, off) \
                if (bit) { float kv = skw[kidx]; float2 v = smV[idx + (off)]; \
                           am += kv; ax += kv * v.x; ay += kv * v.y; }
            ACC(n0 & 1u, 0, -SX-1) ACC(n0 & 2u, 1, -SX) ACC(n0 & 4u, 2, -SX+1)
            ACC(n1 & 1u, 3, -1)                         ACC(n1 & 4u, 5, +1)
            ACC(n2 & 1u, 6,  SX-1) ACC(n2 & 2u, 7,  SX) ACC(n2 & 4u, 8,  SX+1)
            #undef ACC
            smV[idx] = make_float2(ax / am, ay / am);    // own (unset) cell only
        }
        __syncthreads();
        if (act) ((unsigned*)&bmL[wr])[wk] = ((unsigned*)&bmL[wr])[wk] | f;
        __syncthreads();
    }

    // ---- 5 erosion iterations: pure word-level bit ops on 104 threads ----
    for (int it = 0; it < NITER; it++) {
        unsigned nw = 0u;
        if (act) {
            unsigned cw = ((unsigned*)&bmL[wr])[wk];
            unsigned up = (wr > 0)   ? ((unsigned*)&bmL[wr-1])[wk] : 0u;
            unsigned dn = (wr < S-1) ? ((unsigned*)&bmL[wr+1])[wk] : 0u;
            unsigned lw = (wk == 1)  ? ((unsigned*)&bmL[wr])[0]    : 0u;
            unsigned rw = (wk == 0)  ? ((unsigned*)&bmL[wr])[1]    : 0u;
            nw = cw & up & dn & ((cw << 1) | (lw >> 31)) & ((cw >> 1) | (rw << 31));
        }
        __syncthreads();
        if (act) ((unsigned*)&bmL[wr])[wk] = nw;
        __syncthreads();
    }

    // ---- compose interior 32x32, coalesced float2 writes ----
    #pragma unroll
    for (int j = 0; j < (TILE*TILE)/256; j++) {
        int local = tid + j*256;          // 0..1023
        int lyy = local >> 5, lxx = local & 31;
        int rr = lyy + HALO, cc = lxx + HALO;
        bool m = (bmL[rr] >> cc) & 1ull;
        float2 v = smV[rr*SX + cc];
        int py = ty0 + rr, px = tx0 + cc;   // in [0, 512)
        int g = py*W + px;
        float vx = m ? v.x * (2.0f / (float)W) : 4.0f;   // 2*W * (2/W) = 4
        float vy = m ? v.y * (2.0f / (float)H) : 4.0f;
        float2 t2 = tgt[g];
        out[(size_t)b*HW + g] = make_float2(t2.x + vx, t2.y + vy);
    }
}

extern "C" void kernel_launch(void* const* d_in, const int* in_sizes, int n_in,
                              void* d_out, int out_size) {
    // identify inputs by unique element counts (robust to ordering)
    const float* src  = nullptr;   // 8*256*256*2  = 1048576
    const float* kw   = nullptr;   // 3*3          = 9
    const float* base = nullptr;   // 1*256*256*2  = 131072
    const float* tgt  = nullptr;   // 1*512*512*2  = 524288
    for (int j = 0; j < n_in; j++) {
        switch (in_sizes[j]) {
            case 1048576: src  = (const float*)d_in[j]; break;
            case 9:       kw   = (const float*)d_in[j]; break;
            case 131072:  base = (const float*)d_in[j]; break;
            case 524288:  tgt  = (const float*)d_in[j]; break;
            default: break; // niter (size 1) ignored; fixed at 5
        }
    }
    float* out = (float*)d_out;

    const int TB = 256;
    const int n  = (BATCH*HW + TB - 1) / TB;

    k_init   <<<(BATCH*HW/4 + TB - 1)/TB, TB>>>();
    k_compute<<<n, TB>>>((const float2*)src, (const float2*)base);
    k_place  <<<n, TB>>>();

    dim3 grid(W/TILE, H/TILE, BATCH);   // 16 x 16 x 8
    k_fused<<<grid, TB>>>(kw, (const float2*)tgt, (float2*)out);
}

// round 12
// speedup vs baseline: 1.8314x; 1.0073x over previous
#include <cuda_runtime.h>
#include <cstdint>

#define BATCH 8
#define HS 256
#define WS 256
#define H 512
#define W 512
#define HW (H*W)
#define NITER 5

#define TILE 32
#define HALO 10                 // 2*NITER total dependency radius
#define S 52                    // TILE + 2*HALO
#define SX 64                   // padded smem row stride (power of two)
#define SCELLS (S*SX)           // 3328 = 13 * 256 exactly
#define NCL 13                  // cells per thread, no tail
#define WLMAX 2500              // frontier <= interior unset cells (50*50)

#define SENT 2.0e30f
// interior column masks for frontier words: cols 1..50 only
#define MASK_W0 0xFFFFFFFEu     // clear col 0
#define MASK_W1 0x0007FFFFu     // cols 32..50 = bits 0..18

// k_compute tiling: 16x16 quads per CTA, 18x18 cell halo tile
#define QT 16
#define CT 18                   // QT + 2

// ---------------- scratch (static device globals; no runtime allocation) ----------------
__device__ int    g_win[BATCH*HW];
__device__ float2 g_d  [BATCH*HW];
__device__ float2 g_iv [BATCH*HW];   // (-dx,-dy) of winner, or (SENT,SENT) if none

// ---------------- reset winner array (vectorized) ----------------
__global__ void k_init() {
    int t = blockIdx.x * blockDim.x + threadIdx.x;
    int4* p = (int4*)g_win;
    if (t < (BATCH*HW)/4) p[t] = make_int4(0x7FFFFFFF,0x7FFFFFFF,0x7FFFFFFF,0x7FFFFFFF);
}

// ---------------- 2x bilinear upsample of (src - base), scale, scatter winner ----------
// CTA = 16x16 quads; 18x18 (src-base) cell tile staged in smem (weights are {.25,.75}).
__global__ __launch_bounds__(256) void k_compute(const float2* __restrict__ src,
                                                 const float2* __restrict__ base) {
    __shared__ float2 ds[CT*CT];

    int b   = blockIdx.z;
    int qx0 = blockIdx.x * QT;
    int qy0 = blockIdx.y * QT;
    int tid = threadIdx.x;

    const float2* sb = src + (size_t)b * HS * WS;

    // load 18x18 cell tile of (src - base), edge-clamped
    #pragma unroll
    for (int j = 0; j < 2; j++) {
        int idx = tid + j*256;
        if (idx < CT*CT) {
            int row = idx / CT, col = idx - row*CT;
            int gy = min(max(qy0 - 1 + row, 0), HS-1);
            int gx = min(max(qx0 - 1 + col, 0), WS-1);
            int o = gy*WS + gx;
            float2 s = sb[o], bb = base[o];
            ds[idx] = make_float2(s.x - bb.x, s.y - bb.y);
        }
    }
    __syncthreads();

    int tx = tid & 15, ty = tid >> 4;
    int qx = qx0 + tx, qy = qy0 + ty;

    // 3x3 neighborhood from smem
    float2 d00 = ds[(ty+0)*CT + tx+0], d01 = ds[(ty+0)*CT + tx+1], d02 = ds[(ty+0)*CT + tx+2];
    float2 d10 = ds[(ty+1)*CT + tx+0], d11 = ds[(ty+1)*CT + tx+1], d12 = ds[(ty+1)*CT + tx+2];
    float2 d20 = ds[(ty+2)*CT + tx+0], d21 = ds[(ty+2)*CT + tx+1], d22 = ds[(ty+2)*CT + tx+2];

    // row interps: wy = 0.75 for output row 2qy, wy = 0.25 for row 2qy+1
    float2 a0 = make_float2(d00.x*0.25f + d10.x*0.75f, d00.y*0.25f + d10.y*0.75f);
    float2 a1 = make_float2(d01.x*0.25f + d11.x*0.75f, d01.y*0.25f + d11.y*0.75f);
    float2 a2 = make_float2(d02.x*0.25f + d12.x*0.75f, d02.y*0.25f + d12.y*0.75f);
    float2 c0 = make_float2(d10.x*0.75f + d20.x*0.25f, d10.y*0.75f + d20.y*0.25f);
    float2 c1 = make_float2(d11.x*0.75f + d21.x*0.25f, d11.y*0.75f + d21.y*0.25f);
    float2 c2 = make_float2(d12.x*0.75f + d22.x*0.25f, d12.y*0.75f + d22.y*0.25f);

    const float sw = 0.5f * (float)W, sh = 0.5f * (float)H;
    float2 o00 = make_float2((a0.x*0.25f + a1.x*0.75f) * sw, (a0.y*0.25f + a1.y*0.75f) * sh);
    float2 o10 = make_float2((a1.x*0.75f + a2.x*0.25f) * sw, (a1.y*0.75f + a2.y*0.25f) * sh);
    float2 o01 = make_float2((c0.x*0.25f + c1.x*0.75f) * sw, (c0.y*0.25f + c1.y*0.75f) * sh);
    float2 o11 = make_float2((c1.x*0.75f + c2.x*0.25f) * sw, (c1.y*0.75f + c2.y*0.25f) * sh);

    // coalesced float4 stores of (dx,dy) pairs
    int x0 = 2*qx, y0 = 2*qy;
    size_t gbase = (size_t)b*HW;
    *(float4*)&g_d[gbase + (size_t)y0*W + x0]     = make_float4(o00.x, o00.y, o10.x, o10.y);
    *(float4*)&g_d[gbase + (size_t)(y0+1)*W + x0] = make_float4(o01.x, o01.y, o11.x, o11.y);

    // scatter winners: round-half-even (rintf), oob check, winner = min source index
    #define SCATTER(px, py, vv) do {                                               \
        float fx = rintf((float)(px) + (vv).x);                                    \
        float fy = rintf((float)(py) + (vv).y);                                    \
        if (fx >= 0.0f && fy >= 0.0f && fx <= (float)(W-1) && fy <= (float)(H-1)) {\
            int ti = (int)gbase + (int)fy * W + (int)fx;                           \
            atomicMin(&g_win[ti], (py)*W + (px));                                  \
        }                                                                          \
    } while (0)
    SCATTER(x0,   y0,   o00);
    SCATTER(x0+1, y0,   o10);
    SCATTER(x0,   y0+1, o01);
    SCATTER(x0+1, y0+1, o11);
    #undef SCATTER
}

// ---------------- gather winners -> dense float2 with sentinel ----------------
__global__ void k_place() {
    int t = blockIdx.x * blockDim.x + threadIdx.x;
    if (t >= BATCH*HW) return;
    int w = g_win[t];
    int b = t / HW;
    float2 v = make_float2(SENT, SENT);
    if (w != 0x7FFFFFFF) {
        float2 d = g_d[b*HW + w];
        v = make_float2(-d.x, -d.y);
    }
    g_iv[t] = v;
}

// ---------------- fused: 5x dilation (bit frontier -> worklist conv) + 5x bit erosion ----
__global__ __launch_bounds__(256) void k_fused(const float* __restrict__ kw,
                                               const float2* __restrict__ tgt,
                                               float2* __restrict__ out) {
    __shared__ float2             smV[SCELLS];
    __shared__ unsigned long long bm[2][S];     // ping-pong mask bit-planes
    __shared__ unsigned short     wl[WLMAX];    // frontier cell worklist (idx = r*SX + c)
    __shared__ int                wcnt[NITER];  // per-iteration worklist sizes
    __shared__ float              skw[9];

    int b   = blockIdx.z;
    int tx0 = blockIdx.x * TILE - HALO;
    int ty0 = blockIdx.y * TILE - HALO;
    int tid = threadIdx.x;

    if (tid < 9) skw[tid] = kw[tid];
    if (tid < NITER) wcnt[tid] = 0;

    // thread-invariant column; r for cell j is r0 + 4*j
    const int c    = tid & 63;
    const int r0   = tid >> 6;
    const int half = (tid >> 5) & 1;          // which 32-col word this warp covers

    const float2* giv = g_iv + (size_t)b * HW;

    // ---- load 52x52 tile (zero-extended), build mask bitwords via ballot ----
    #pragma unroll
    for (int j = 0; j < NCL; j++) {
        int idx = tid + j*256;
        int r = r0 + 4*j;
        float2 v = make_float2(0.0f, 0.0f);
        bool m = false;
        if (c < S) {
            int px = tx0 + c, py = ty0 + r;
            if (px >= 0 && px < W && py >= 0 && py < H) {
                float2 g = giv[py*W + px];
                if (g.x != SENT) { v = g; m = true; }
            }
        }
        smV[idx] = v;
        unsigned wball = __ballot_sync(0xffffffffu, m);
        if ((tid & 31) == 0) ((unsigned*)&bm[0][r])[half] = wball;
    }
    __syncthreads();

    const bool act = tid < S*2;
    const int  wr  = tid >> 1, wk = tid & 1;
    int cur = 0;

    // ---- 5 dilation iterations: frontier+next-plane phase, then worklist conv ----
    for (int it = 0; it < NITER; it++) {
        if (act) {
            unsigned cw = ((unsigned*)&bm[cur][wr])[wk];
            unsigned up = (wr > 0)   ? ((unsigned*)&bm[cur][wr-1])[wk] : 0u;
            unsigned dn = (wr < S-1) ? ((unsigned*)&bm[cur][wr+1])[wk] : 0u;
            unsigned lw = (wk == 1)  ? ((unsigned*)&bm[cur][wr])[0]    : 0u;
            unsigned rw = (wk == 0)  ? ((unsigned*)&bm[cur][wr])[1]    : 0u;
            unsigned f = (up | dn | (cw << 1) | (lw >> 31) | (cw >> 1) | (rw << 31)) & ~cw;
            f &= wk ? MASK_W1 : MASK_W0;
            if (wr == 0 || wr == S-1) f = 0u;
            ((unsigned*)&bm[cur^1][wr])[wk] = cw | f;     // next plane
            if (f) {
                int ofs = atomicAdd(&wcnt[it], __popc(f));
                unsigned ff = f;
                int cellbase = wr*SX + wk*32;
                while (ff) {
                    int bit = __ffs(ff) - 1;
                    ff &= ff - 1;
                    wl[ofs++] = (unsigned short)(cellbase + bit);
                }
            }
        }
        __syncthreads();

        // conv at listed frontier cells only (gates read the OLD plane bm[cur])
        int n = wcnt[it];
        for (int k = tid; k < n; k += 256) {
            int idx = wl[k];
            int cc = idx & 63;              // in [1,50]
            int rr = idx >> 6;              // in [1,50]
            unsigned long long rm = bm[cur][rr-1], rc = bm[cur][rr], rp = bm[cur][rr+1];
            unsigned n0 = (unsigned)(rm >> (cc-1)) & 7u;
            unsigned n1 = (unsigned)(rc >> (cc-1)) & 7u;   // center bit = 0 by construction
            unsigned n2 = (unsigned)(rp >> (cc-1)) & 7u;
            float am = 0.0f, ax = 0.0f, ay = 0.0f;
            #define ACC(bit, kidx, off) \
                if (bit) { float kv = skw[kidx]; float2 v = smV[idx + (off)]; \
                           am += kv; ax += kv * v.x; ay += kv * v.y; }
            ACC(n0 & 1u, 0, -SX-1) ACC(n0 & 2u, 1, -SX) ACC(n0 & 4u, 2, -SX+1)
            ACC(n1 & 1u, 3, -1)                         ACC(n1 & 4u, 5, +1)
            ACC(n2 & 1u, 6,  SX-1) ACC(n2 & 2u, 7,  SX) ACC(n2 & 4u, 8,  SX+1)
            #undef ACC
            smV[idx] = make_float2(ax / am, ay / am);    // own (unset) cell only
        }
        __syncthreads();
        cur ^= 1;
    }

    // ---- 5 erosion iterations: 1 sync each (ping-pong planes) ----
    for (int it = 0; it < NITER; it++) {
        if (act) {
            unsigned cw = ((unsigned*)&bm[cur][wr])[wk];
            unsigned up = (wr > 0)   ? ((unsigned*)&bm[cur][wr-1])[wk] : 0u;
            unsigned dn = (wr < S-1) ? ((unsigned*)&bm[cur][wr+1])[wk] : 0u;
            unsigned lw = (wk == 1)  ? ((unsigned*)&bm[cur][wr])[0]    : 0u;
            unsigned rw = (wk == 0)  ? ((unsigned*)&bm[cur][wr])[1]    : 0u;
            ((unsigned*)&bm[cur^1][wr])[wk] =
                cw & up & dn & ((cw << 1) | (lw >> 31)) & ((cw >> 1) | (rw << 31));
        }
        __syncthreads();
        cur ^= 1;
    }

    // ---- compose interior 32x32, coalesced float2 writes ----
    #pragma unroll
    for (int j = 0; j < (TILE*TILE)/256; j++) {
        int local = tid + j*256;          // 0..1023
        int lyy = local >> 5, lxx = local & 31;
        int rr = lyy + HALO, cc = lxx + HALO;
        bool m = (bm[cur][rr] >> cc) & 1ull;
        float2 v = smV[rr*SX + cc];
        int py = ty0 + rr, px = tx0 + cc;   // in [0, 512)
        int g = py*W + px;
        float vx = m ? v.x * (2.0f / (float)W) : 4.0f;   // 2*W * (2/W) = 4
        float vy = m ? v.y * (2.0f / (float)H) : 4.0f;
        float2 t2 = tgt[g];
        out[(size_t)b*HW + g] = make_float2(t2.x + vx, t2.y + vy);
    }
}

extern "C" void kernel_launch(void* const* d_in, const int* in_sizes, int n_in,
                              void* d_out, int out_size) {
    // identify inputs by unique element counts (robust to ordering)
    const float* src  = nullptr;   // 8*256*256*2  = 1048576
    const float* kw   = nullptr;   // 3*3          = 9
    const float* base = nullptr;   // 1*256*256*2  = 131072
    const float* tgt  = nullptr;   // 1*512*512*2  = 524288
    for (int j = 0; j < n_in; j++) {
        switch (in_sizes[j]) {
            case 1048576: src  = (const float*)d_in[j]; break;
            case 9:       kw   = (const float*)d_in[j]; break;
            case 131072:  base = (const float*)d_in[j]; break;
            case 524288:  tgt  = (const float*)d_in[j]; break;
            default: break; // niter (size 1) ignored; fixed at 5
        }
    }
    float* out = (float*)d_out;

    const int TB = 256;
    const int n  = (BATCH*HW + TB - 1) / TB;

    k_init   <<<(BATCH*HW/4 + TB - 1)/TB, TB>>>();
    dim3 cgrid(WS/QT, HS/QT, BATCH);    // 16 x 16 x 8
    k_compute<<<cgrid, TB>>>((const float2*)src, (const float2*)base);
    k_place  <<<n, TB>>>();

    dim3 grid(W/TILE, H/TILE, BATCH);   // 16 x 16 x 8
    k_fused<<<grid, TB>>>(kw, (const float2*)tgt, (float2*)out);
}